// round 13
// baseline (speedup 1.0000x reference)
#include <cuda_runtime.h>
#include <cstdint>

typedef unsigned long long ull;

// ---------------- problem constants ----------------
#define NS 32
#define NT 64
#define NB 64
#define NROWS1 (NS*NT*NB)   // 131072
#define NROWS2 (NS*NB)      // 2048
#define NV 32000

// ---------------- scratch (device globals) ----------------
__device__ ulonglong2 g_Wih1p[2*32*384];   // [d][q<32][g]: k-pairs of Wih_intra
__device__ ulonglong2 g_Whh1p[2*32*384];
__device__ ulonglong2 g_WW1p [64*256];     // [q<64][k]
__device__ ulonglong2 g_Wih2p[2*64*384];
__device__ ulonglong2 g_Whh2p[2*32*384];
__device__ ulonglong2 g_WW2p [64*256];

__device__ float g_vg    [(size_t)NV*768];  // vocab input-gates: [v][d*384+g]
__device__ float g_out1  [(size_t)NROWS1*256];
__device__ float g_scores1[NROWS1];
__device__ float g_alpha1 [NROWS1];
__device__ float g_sent  [NROWS2*256];
__device__ float g_xg2   [2*NROWS2*384];
__device__ float g_out2  [NROWS2*256];
__device__ float g_scores2[NROWS2];
__device__ float g_doc   [NB*256];

// ---------------- helpers ----------------
__device__ __forceinline__ ull ff2(ull a, ull b, ull c) {
    ull d;
    asm("fma.rn.f32x2 %0, %1, %2, %3;" : "=l"(d) : "l"(a), "l"(b), "l"(c));
    return d;
}
__device__ __forceinline__ float2 up2(ull v) {
    float2 f;
    asm("mov.b64 {%0, %1}, %2;" : "=f"(f.x), "=f"(f.y) : "l"(v));
    return f;
}
__device__ __forceinline__ float sigm(float x) {
    return __fdividef(1.f, 1.f + __expf(-x));
}
__device__ __forceinline__ float tanha(float x) {
    float ax = fabsf(x);
    float e  = __expf(-2.f * ax);
    float t  = (1.f - e) * __fdividef(1.f, 1.f + e);
    return copysignf(t, x);
}

// ---------------- K0: pack weights into k-pair (f32x2) layouts ----------------
__global__ void k_pack(const float* __restrict__ Wih1, const float* __restrict__ Whh1,
                       const float* __restrict__ WW1,  const float* __restrict__ Wih2,
                       const float* __restrict__ Whh2, const float* __restrict__ WW2) {
    const int total = 24576 + 24576 + 16384 + 49152 + 24576 + 16384;
    for (int n = blockIdx.x * blockDim.x + threadIdx.x; n < total; n += gridDim.x * blockDim.x) {
        int m = n;
        if (m < 24576) {
            int d = m / (32*384), r = m % (32*384), q = r / 384, g = r % 384;
            const float* w = Wih1 + (d*384 + g)*128 + 4*q;
            ((float4*)g_Wih1p)[m] = make_float4(w[0], w[1], w[2], w[3]);
            continue;
        } m -= 24576;
        if (m < 24576) {
            int d = m / (32*384), r = m % (32*384), q = r / 384, g = r % 384;
            const float* w = Whh1 + (d*384 + g)*128 + 4*q;
            ((float4*)g_Whh1p)[m] = make_float4(w[0], w[1], w[2], w[3]);
            continue;
        } m -= 24576;
        if (m < 16384) {
            int q = m / 256, k = m % 256;
            ((float4*)g_WW1p)[m] = make_float4(WW1[(4*q+0)*256+k], WW1[(4*q+1)*256+k],
                                               WW1[(4*q+2)*256+k], WW1[(4*q+3)*256+k]);
            continue;
        } m -= 16384;
        if (m < 49152) {
            int d = m / (64*384), r = m % (64*384), q = r / 384, g = r % 384;
            const float* w = Wih2 + (d*384 + g)*256 + 4*q;
            ((float4*)g_Wih2p)[m] = make_float4(w[0], w[1], w[2], w[3]);
            continue;
        } m -= 49152;
        if (m < 24576) {
            int d = m / (32*384), r = m % (32*384), q = r / 384, g = r % 384;
            const float* w = Whh2 + (d*384 + g)*128 + 4*q;
            ((float4*)g_Whh2p)[m] = make_float4(w[0], w[1], w[2], w[3]);
            continue;
        } m -= 24576;
        {
            int q = m / 256, k = m % 256;
            ((float4*)g_WW2p)[m] = make_float4(WW2[(4*q+0)*256+k], WW2[(4*q+1)*256+k],
                                               WW2[(4*q+2)*256+k], WW2[(4*q+3)*256+k]);
        }
    }
}

// ---------------- K1: vocab input-gate table: vg[v] = embed[v] @ Wih^T + bih ----------------
// block = 16 vocab rows, 384 threads (one g-col each, both dirs), 16 rows per thread.
// Per q: 2 LDG + 16 LDS(broadcast) + 64 FFMA2.
__global__ void __launch_bounds__(384) k_vg(const float* __restrict__ emb,
                                            const float* __restrict__ bih) {
    __shared__ __align__(16) float xs[16][128];
    const int rb = blockIdx.x, tid = threadIdx.x;
    for (int u = tid; u < 512; u += 384) {
        int i = u >> 5, f = u & 31;
        ((float4*)xs[i])[f] = ((const float4*)emb)[(size_t)(rb*16 + i)*32 + f];
    }
    __syncthreads();
    const int g = tid;
    ull acc[32];
#pragma unroll
    for (int i = 0; i < 32; i++) acc[i] = 0ull;
    ulonglong2 w0 = g_Wih1p[g];
    ulonglong2 w1 = g_Wih1p[32*384 + g];
#pragma unroll 1
    for (int q = 0; q < 32; q++) {
        ulonglong2 c0 = w0, c1 = w1;
        int qn = (q + 1) & 31;
        w0 = g_Wih1p[qn*384 + g];
        w1 = g_Wih1p[32*384 + qn*384 + g];
#pragma unroll
        for (int i = 0; i < 16; i++) {
            ulonglong2 x = ((const ulonglong2*)xs[i])[q];
            acc[2*i]   = ff2(x.x, c0.x, acc[2*i]);
            acc[2*i]   = ff2(x.y, c0.y, acc[2*i]);
            acc[2*i+1] = ff2(x.x, c1.x, acc[2*i+1]);
            acc[2*i+1] = ff2(x.y, c1.y, acc[2*i+1]);
        }
    }
    const float b0 = bih[g], b1 = bih[384 + g];
#pragma unroll
    for (int i = 0; i < 16; i++) {
        float2 f0 = up2(acc[2*i]);
        float2 f1 = up2(acc[2*i+1]);
        size_t v = (size_t)(rb*16 + i);
        g_vg[v*768 + g]       = f0.x + f0.y + b0;
        g_vg[v*768 + 384 + g] = f1.x + f1.y + b1;
    }
}

// ---------------- K2: intra biGRU, persistent per (sentence, dir, batch-half) ----------------
// grid (2 bc, 2 d, 32 s) = 128 blocks, 256 threads: thread = (j<128, rowgroup<2 of 16 rows).
// 64 KB dynamic smem: hsm[32][128] + xg[32][384]. Weight LDG double-buffered; each weight
// load feeds 16 rows -> L1 wavefronts ~ balanced with FFMA2.
__global__ void __launch_bounds__(256, 1) k_gru1(const float* __restrict__ bhh,
                                                 const int* __restrict__ tok) {
    extern __shared__ __align__(16) float dsm[];
    float (*hsm)[128] = (float(*)[128])dsm;            // 32*128 = 16 KB
    float (*xg)[384]  = (float(*)[384])(dsm + 32*128); // 32*384 = 48 KB
    const int bc = blockIdx.x, d = blockIdx.y, s = blockIdx.z, tid = threadIdx.x;
    const int j = tid & 127, rg = tid >> 7;            // rows rg*16 .. rg*16+15
    for (int u = tid; u < 32*128; u += 256) ((float*)hsm)[u] = 0.f;
    const ulonglong2* wp = g_Whh1p + d*(32*384);
    const float bh_r = bhh[d*384 + j];
    const float bh_z = bhh[d*384 + 128 + j];
    const float bh_n = bhh[d*384 + 256 + j];
    __syncthreads();

    // prefetch step TT's gate rows into xg: 32 rows x 96 float4 = 3072, 12 per thread
    #define PREFETCH(TT) do {                                                        \
        _Pragma("unroll")                                                            \
        for (int r_ = 0; r_ < 12; r_++) {                                            \
            int u_ = tid + 256*r_;                                                   \
            int i_ = u_ / 96, c_ = u_ % 96;                                          \
            int tk_ = tok[(size_t)(s*64 + (TT))*64 + bc*32 + i_];                    \
            const float4* src_ = (const float4*)(g_vg + (size_t)tk_*768 + d*384) + c_;\
            uint32_t da_ = (uint32_t)__cvta_generic_to_shared(&xg[i_][c_*4]);        \
            asm volatile("cp.async.cg.shared.global [%0], [%1], 16;"                 \
                         :: "r"(da_), "l"(src_));                                    \
        }                                                                            \
        asm volatile("cp.async.commit_group;");                                      \
    } while (0)

    PREFETCH(d ? 63 : 0);
    for (int t = 0; t < 64; t++) {
        const int tt = d ? 63 - t : t;
        // ---- phase A: gh = h @ Whh^T (3 gates x 16 rows per thread) ----
        ull a[48];
#pragma unroll
        for (int i = 0; i < 48; i++) a[i] = 0ull;
        ulonglong2 wr = wp[j], wz = wp[128 + j], wn = wp[256 + j];
#pragma unroll 1
        for (int q = 0; q < 32; q++) {
            ulonglong2 cr = wr, cz = wz, cn = wn;
            int qn = (q + 1) & 31;
            wr = wp[qn*384 + j];
            wz = wp[qn*384 + 128 + j];
            wn = wp[qn*384 + 256 + j];
#pragma unroll
            for (int i = 0; i < 16; i++) {
                ulonglong2 x = ((const ulonglong2*)hsm[rg*16 + i])[q];
                a[3*i+0] = ff2(x.x, cr.x, a[3*i+0]);
                a[3*i+0] = ff2(x.y, cr.y, a[3*i+0]);
                a[3*i+1] = ff2(x.x, cz.x, a[3*i+1]);
                a[3*i+1] = ff2(x.y, cz.y, a[3*i+1]);
                a[3*i+2] = ff2(x.x, cn.x, a[3*i+2]);
                a[3*i+2] = ff2(x.y, cn.y, a[3*i+2]);
            }
        }
        asm volatile("cp.async.wait_group 0;");
        __syncthreads();   // phase-A hsm reads done; xg landed
        // ---- phase B: gates + state update (same thread holds its rows' accs) ----
#pragma unroll
        for (int i = 0; i < 16; i++) {
            const int row = rg*16 + i;
            float2 fr = up2(a[3*i+0]);
            float2 fz = up2(a[3*i+1]);
            float2 fn = up2(a[3*i+2]);
            float r = sigm(xg[row][j]       + fr.x + fr.y + bh_r);
            float z = sigm(xg[row][128 + j] + fz.x + fz.y + bh_z);
            float n = tanha(xg[row][256 + j] + r * (fn.x + fn.y + bh_n));
            float hp = hsm[row][j];
            float hn = (1.f - z) * n + z * hp;
            hsm[row][j] = hn;
            g_out1[((size_t)(s*64 + tt)*64 + bc*32 + row)*256 + d*128 + j] = hn;
        }
        __syncthreads();   // xg free, hsm settled
        if (t + 1 < 64) PREFETCH(d ? 63 - (t+1) : t+1);
    }
    #undef PREFETCH
}

// ---------------- K3/K8: attention score = proj . tanh(x @ W + b), fused ----------------
// block = 16 rows, 256 threads = (k<128, rg<2). Thread: cols k, k+128 x 8 rows.
// q-loop unrolled x2 to amortize address ALU.
__global__ void __launch_bounds__(256, 3) k_score(int level, const float* __restrict__ bias,
                                                  const float* __restrict__ proj) {
    __shared__ __align__(16) float xs[16][256];
    __shared__ float red[16][4];
    const float* x       = level ? g_out2 : g_out1;
    const ulonglong2* wp = level ? g_WW2p : g_WW1p;
    float* out           = level ? g_scores2 : g_scores1;
    const int rb = blockIdx.x, tid = threadIdx.x;
    const int k = tid & 127, rg = tid >> 7;
    for (int u = tid; u < 16*64; u += 256) {
        int i = u >> 6, f = u & 63;
        ((float4*)xs[i])[f] = ((const float4*)x)[(size_t)(rb*16 + i)*64 + f];
    }
    __syncthreads();
    ull acc[16];
#pragma unroll
    for (int i = 0; i < 16; i++) acc[i] = 0ull;
#pragma unroll 2
    for (int q = 0; q < 64; q++) {
        ulonglong2 w0 = wp[q*256 + k];
        ulonglong2 w1 = wp[q*256 + 128 + k];
#pragma unroll
        for (int i = 0; i < 8; i++) {
            ulonglong2 xv = ((const ulonglong2*)xs[rg*8 + i])[q];
            acc[2*i]   = ff2(xv.x, w0.x, acc[2*i]);
            acc[2*i]   = ff2(xv.y, w0.y, acc[2*i]);
            acc[2*i+1] = ff2(xv.x, w1.x, acc[2*i+1]);
            acc[2*i+1] = ff2(xv.y, w1.y, acc[2*i+1]);
        }
    }
    const float b0 = bias[k], b1 = bias[128 + k];
    const float p0 = proj[k], p1 = proj[128 + k];
    const int lane = tid & 31, wrp4 = (tid >> 5) & 3;
#pragma unroll 1
    for (int i = 0; i < 8; i++) {
        float2 f0 = up2(acc[2*i]);
        float2 f1 = up2(acc[2*i+1]);
        float v = tanha(f0.x + f0.y + b0) * p0 + tanha(f1.x + f1.y + b1) * p1;
#pragma unroll
        for (int o = 16; o > 0; o >>= 1) v += __shfl_xor_sync(0xffffffffu, v, o);
        if (lane == 0) red[rg*8 + i][wrp4] = v;
    }
    __syncthreads();
    if (tid < 16) {
        float sm = red[tid][0] + red[tid][1] + red[tid][2] + red[tid][3];
        out[rb*16 + tid] = sm;
    }
}

// ---------------- K4: softmax over tokens ----------------
__global__ void k_softmax() {
    const int s = blockIdx.x, b = threadIdx.x;
    const float* sc = g_scores1 + (size_t)s*64*64 + b;
    float m = -1e30f;
    for (int t = 0; t < 64; t++) m = fmaxf(m, sc[(size_t)t*64]);
    float sum = 0.f;
    for (int t = 0; t < 64; t++) sum += __expf(sc[(size_t)t*64] - m);
    float inv = __fdividef(1.f, sum);
    float* al = g_alpha1 + (size_t)s*64*64 + b;
    for (int t = 0; t < 64; t++) al[(size_t)t*64] = __expf(sc[(size_t)t*64] - m) * inv;
}

// ---------------- K5: sentence vectors ----------------
__global__ void k_sent() {
    const int blk = blockIdx.x, s = blk >> 6, b = blk & 63, h = threadIdx.x;
    float acc = 0.f;
    for (int t = 0; t < 64; t++) {
        float a = g_alpha1[(size_t)(s*64 + t)*64 + b];
        acc += a * g_out1[((size_t)(s*64 + t)*64 + b)*256 + h];
    }
    g_sent[(size_t)(s*64 + b)*256 + h] = acc;
}

// ---------------- K6: input-gate GEMM (inter), K=256 ----------------
__global__ void __launch_bounds__(384) k_xg2(const float* __restrict__ bih2) {
    __shared__ __align__(16) float xs[16][256];
    const int rb = blockIdx.x, d = blockIdx.y, tid = threadIdx.x;
    for (int u = tid; u < 16*64; u += 384) {
        int i = u >> 6, f = u & 63;
        ((float4*)xs[i])[f] = ((const float4*)g_sent)[(size_t)(rb*16 + i)*64 + f];
    }
    __syncthreads();
    const int g2 = tid % 192, rg = tid / 192;
    ull acc[16];
#pragma unroll
    for (int i = 0; i < 16; i++) acc[i] = 0ull;
    const ulonglong2* wp = g_Wih2p + d*(64*384);
#pragma unroll 1
    for (int q = 0; q < 64; q++) {
        ulonglong2 w0 = wp[q*384 + g2];
        ulonglong2 w1 = wp[q*384 + 192 + g2];
#pragma unroll
        for (int i = 0; i < 8; i++) {
            ulonglong2 x = ((const ulonglong2*)xs[rg*8 + i])[q];
            acc[2*i]   = ff2(x.x, w0.x, acc[2*i]);
            acc[2*i]   = ff2(x.y, w0.y, acc[2*i]);
            acc[2*i+1] = ff2(x.x, w1.x, acc[2*i+1]);
            acc[2*i+1] = ff2(x.y, w1.y, acc[2*i+1]);
        }
    }
    const float b0 = bih2[d*384 + g2], b1 = bih2[d*384 + 192 + g2];
#pragma unroll
    for (int i = 0; i < 8; i++) {
        float2 f0 = up2(acc[2*i]);
        float2 f1 = up2(acc[2*i+1]);
        float* op = g_xg2 + ((size_t)d*NROWS2 + rb*16 + rg*8 + i)*384;
        op[g2]       = f0.x + f0.y + b0;
        op[192 + g2] = f1.x + f1.y + b1;
    }
}

// ---------------- K7: inter biGRU (32 steps, BCHUNK=4) ----------------
__global__ void __launch_bounds__(384, 2) k_gru2(const float* __restrict__ bhh2) {
    __shared__ __align__(16) float hsm[4][128];
    __shared__ float ghs[4][384];
    const int bc = blockIdx.x, d = blockIdx.y, tid = threadIdx.x;
    for (int u = tid; u < 4*128; u += 384) ((float*)hsm)[u] = 0.f;
    const float bh = bhh2[d*384 + tid];
    const ulonglong2* wp = g_Whh2p + d*(32*384);
    __syncthreads();
    for (int t = 0; t < 32; t++) {
        const int tt = d ? (31 - t) : t;
        {
            const int g = tid;
            ull acc[4];
#pragma unroll
            for (int i = 0; i < 4; i++) acc[i] = 0ull;
#pragma unroll 1
            for (int q = 0; q < 32; q++) {
                ulonglong2 w = wp[q*384 + g];
#pragma unroll
                for (int i = 0; i < 4; i++) {
                    ulonglong2 x = ((const ulonglong2*)hsm[i])[q];
                    acc[i] = ff2(x.x, w.x, acc[i]);
                    acc[i] = ff2(x.y, w.y, acc[i]);
                }
            }
#pragma unroll
            for (int i = 0; i < 4; i++) {
                float2 f = up2(acc[i]);
                ghs[i][g] = f.x + f.y + bh;
            }
        }
        __syncthreads();
        if (tid < 128) {
            const int j = tid;
#pragma unroll 1
            for (int i = 0; i < 4; i++) {
                const int b = bc*4 + i;
                const float* xr = g_xg2 + ((size_t)d*NROWS2 + (size_t)tt*64 + b)*384;
                float r = sigm(xr[j]       + ghs[i][j]);
                float z = sigm(xr[128 + j] + ghs[i][128 + j]);
                float n = tanha(xr[256 + j] + r * ghs[i][256 + j]);
                float hp = hsm[i][j];
                float hn = (1.f - z) * n + z * hp;
                hsm[i][j] = hn;
                g_out2[((size_t)tt*64 + b)*256 + d*128 + j] = hn;
            }
        }
        __syncthreads();
    }
}

// ---------------- K9: doc vector ----------------
__global__ void k_doc() {
    const int b = blockIdx.x, h = threadIdx.x;
    float acc = 0.f;
    for (int s = 0; s < 32; s++)
        acc += g_scores2[s*64 + b] * g_out2[((size_t)(s*64 + b))*256 + h];
    g_doc[b*256 + h] = acc;
}

// ---------------- K10: final linear [64,5] ----------------
__global__ void k_final(const float* __restrict__ Wf, const float* __restrict__ bf,
                        float* __restrict__ out) {
    const int tid = threadIdx.x;
    if (tid >= 320) return;
    const int b = tid / 5, c = tid % 5;
    float acc = bf[c];
    for (int h = 0; h < 256; h++) acc += g_doc[b*256 + h] * Wf[c*256 + h];
    out[b*5 + c] = acc;
}

// ---------------- launch ----------------
extern "C" void kernel_launch(void* const* d_in, const int* in_sizes, int n_in,
                              void* d_out, int out_size) {
    const int*   tokens = (const int*)  d_in[0];
    const float* emb    = (const float*)d_in[1];
    const float* Wih1   = (const float*)d_in[2];
    const float* Whh1   = (const float*)d_in[3];
    const float* bih1   = (const float*)d_in[4];
    const float* bhh1   = (const float*)d_in[5];
    const float* WW1    = (const float*)d_in[6];
    const float* b1     = (const float*)d_in[7];
    const float* p1     = (const float*)d_in[8];
    const float* Wih2   = (const float*)d_in[9];
    const float* Whh2   = (const float*)d_in[10];
    const float* bih2   = (const float*)d_in[11];
    const float* bhh2   = (const float*)d_in[12];
    const float* WW2    = (const float*)d_in[13];
    const float* b2     = (const float*)d_in[14];
    const float* p2     = (const float*)d_in[15];
    const float* Wf     = (const float*)d_in[16];
    const float* bf     = (const float*)d_in[17];
    float* out = (float*)d_out;

    static int smem_set = 0;
    if (!smem_set) {
        cudaFuncSetAttribute(k_gru1, cudaFuncAttributeMaxDynamicSharedMemorySize, 65536);
        smem_set = 1;
    }

    k_pack   <<<152, 256>>>(Wih1, Whh1, WW1, Wih2, Whh2, WW2);
    k_vg     <<<2000, 384>>>(emb, bih1);
    k_gru1   <<<dim3(2, 2, 32), 256, 65536>>>(bhh1, tokens);
    k_score  <<<8192, 256>>>(0, b1, p1);
    k_softmax<<<32, 64>>>();
    k_sent   <<<2048, 256>>>();
    k_xg2    <<<dim3(128, 2), 384>>>(bih2);
    k_gru2   <<<dim3(16, 2), 384>>>(bhh2);
    k_score  <<<128, 256>>>(1, b2, p2);
    k_doc    <<<64, 256>>>();
    k_final  <<<1, 512>>>(Wf, bf, out);
}

// round 15
// speedup vs baseline: 1.1199x; 1.1199x over previous
#include <cuda_runtime.h>
#include <cstdint>

typedef unsigned long long ull;

// ---------------- problem constants ----------------
#define NS 32
#define NT 64
#define NB 64
#define NROWS1 (NS*NT*NB)   // 131072
#define NROWS2 (NS*NB)      // 2048
#define NV 32000

// ---------------- scratch (device globals) ----------------
__device__ ulonglong2 g_Wih1p[2*32*384];   // [d][q<32][g]: k-pairs of Wih_intra
__device__ ulonglong2 g_Whh1p[2*32*384];
__device__ ulonglong2 g_WW1p [64*256];     // [q<64][k]
__device__ ulonglong2 g_Wih2p[2*64*384];
__device__ ulonglong2 g_Whh2p[2*32*384];
__device__ ulonglong2 g_WW2p [64*256];

__device__ float g_vg    [(size_t)NV*768];  // vocab input-gates: [v][d*384+g]
__device__ float g_out1  [(size_t)NROWS1*256];
__device__ float g_scores1[NROWS1];
__device__ float g_alpha1 [NROWS1];
__device__ float g_sent  [NROWS2*256];
__device__ float g_xg2   [2*NROWS2*384];
__device__ float g_out2  [NROWS2*256];
__device__ float g_scores2[NROWS2];
__device__ float g_doc   [NB*256];

// ---------------- helpers ----------------
__device__ __forceinline__ ull ff2(ull a, ull b, ull c) {
    ull d;
    asm("fma.rn.f32x2 %0, %1, %2, %3;" : "=l"(d) : "l"(a), "l"(b), "l"(c));
    return d;
}
__device__ __forceinline__ float2 up2(ull v) {
    float2 f;
    asm("mov.b64 {%0, %1}, %2;" : "=f"(f.x), "=f"(f.y) : "l"(v));
    return f;
}
__device__ __forceinline__ float sigm(float x) {
    return __fdividef(1.f, 1.f + __expf(-x));
}
__device__ __forceinline__ float tanha(float x) {
    float ax = fabsf(x);
    float e  = __expf(-2.f * ax);
    float t  = (1.f - e) * __fdividef(1.f, 1.f + e);
    return copysignf(t, x);
}

// ---------------- K0: pack weights into k-pair (f32x2) layouts ----------------
__global__ void k_pack(const float* __restrict__ Wih1, const float* __restrict__ Whh1,
                       const float* __restrict__ WW1,  const float* __restrict__ Wih2,
                       const float* __restrict__ Whh2, const float* __restrict__ WW2) {
    const int total = 24576 + 24576 + 16384 + 49152 + 24576 + 16384;
    for (int n = blockIdx.x * blockDim.x + threadIdx.x; n < total; n += gridDim.x * blockDim.x) {
        int m = n;
        if (m < 24576) {
            int d = m / (32*384), r = m % (32*384), q = r / 384, g = r % 384;
            const float* w = Wih1 + (d*384 + g)*128 + 4*q;
            ((float4*)g_Wih1p)[m] = make_float4(w[0], w[1], w[2], w[3]);
            continue;
        } m -= 24576;
        if (m < 24576) {
            int d = m / (32*384), r = m % (32*384), q = r / 384, g = r % 384;
            const float* w = Whh1 + (d*384 + g)*128 + 4*q;
            ((float4*)g_Whh1p)[m] = make_float4(w[0], w[1], w[2], w[3]);
            continue;
        } m -= 24576;
        if (m < 16384) {
            int q = m / 256, k = m % 256;
            ((float4*)g_WW1p)[m] = make_float4(WW1[(4*q+0)*256+k], WW1[(4*q+1)*256+k],
                                               WW1[(4*q+2)*256+k], WW1[(4*q+3)*256+k]);
            continue;
        } m -= 16384;
        if (m < 49152) {
            int d = m / (64*384), r = m % (64*384), q = r / 384, g = r % 384;
            const float* w = Wih2 + (d*384 + g)*256 + 4*q;
            ((float4*)g_Wih2p)[m] = make_float4(w[0], w[1], w[2], w[3]);
            continue;
        } m -= 49152;
        if (m < 24576) {
            int d = m / (32*384), r = m % (32*384), q = r / 384, g = r % 384;
            const float* w = Whh2 + (d*384 + g)*128 + 4*q;
            ((float4*)g_Whh2p)[m] = make_float4(w[0], w[1], w[2], w[3]);
            continue;
        } m -= 24576;
        {
            int q = m / 256, k = m % 256;
            ((float4*)g_WW2p)[m] = make_float4(WW2[(4*q+0)*256+k], WW2[(4*q+1)*256+k],
                                               WW2[(4*q+2)*256+k], WW2[(4*q+3)*256+k]);
        }
    }
}

// ---------------- K1: vocab input-gate table: vg[v] = embed[v] @ Wih^T + bih ----------------
// block = 16 vocab rows, 768 threads = (g<384, rg<2). Thread: 2 cols (dir0/dir1, col g)
// x 8 rows -> per q: 2 LDG + 8 LDS + 32 FFMA2.  (R11 version — measured best)
__global__ void __launch_bounds__(768) k_vg(const float* __restrict__ emb,
                                            const float* __restrict__ bih) {
    __shared__ __align__(16) float xs[16][128];
    const int rb = blockIdx.x, tid = threadIdx.x;
    if (tid < 512) {
        int i = tid >> 5, f = tid & 31;
        ((float4*)xs[i])[f] = ((const float4*)emb)[(size_t)(rb*16 + i)*32 + f];
    }
    __syncthreads();
    const int g = tid % 384, rg = tid / 384;    // rows rg*8 .. rg*8+7
    ull acc[16];
#pragma unroll
    for (int i = 0; i < 16; i++) acc[i] = 0ull;
#pragma unroll 1
    for (int q = 0; q < 32; q++) {
        ulonglong2 w0 = g_Wih1p[q*384 + g];
        ulonglong2 w1 = g_Wih1p[32*384 + q*384 + g];
#pragma unroll
        for (int i = 0; i < 8; i++) {
            ulonglong2 x = ((const ulonglong2*)xs[rg*8 + i])[q];
            acc[2*i]   = ff2(x.x, w0.x, acc[2*i]);
            acc[2*i]   = ff2(x.y, w0.y, acc[2*i]);
            acc[2*i+1] = ff2(x.x, w1.x, acc[2*i+1]);
            acc[2*i+1] = ff2(x.y, w1.y, acc[2*i+1]);
        }
    }
    const float b0 = bih[g], b1 = bih[384 + g];
#pragma unroll
    for (int i = 0; i < 8; i++) {
        float2 f0 = up2(acc[2*i]);
        float2 f1 = up2(acc[2*i+1]);
        size_t v = (size_t)(rb*16 + rg*8 + i);
        g_vg[v*768 + g]       = f0.x + f0.y + b0;
        g_vg[v*768 + 384 + g] = f1.x + f1.y + b1;
    }
}

// ---------------- K2: intra biGRU, persistent per (sentence, dir, batch-chunk) ----------------
// grid (4 bc, 2 d, 32 s) = 256 blocks, 512 threads: thread = (j<128, rowgroup<4 of 4 rows).
// Input gates for the NEXT step are prefetched into smem via cp.async during phase A.
// (R11 version — measured best)
__global__ void __launch_bounds__(512, 2) k_gru1(const float* __restrict__ bhh,
                                                 const int* __restrict__ tok) {
    __shared__ __align__(16) float hsm[16][128];
    __shared__ __align__(16) float xg[16][384];
    const int bc = blockIdx.x, d = blockIdx.y, s = blockIdx.z, tid = threadIdx.x;
    const int j = tid & 127, rg = tid >> 7;      // rows rg*4 .. rg*4+3
    for (int u = tid; u < 16*128; u += 512) ((float*)hsm)[u] = 0.f;
    const ulonglong2* wp = g_Whh1p + d*(32*384);
    const float bh_r = bhh[d*384 + j];
    const float bh_z = bhh[d*384 + 128 + j];
    const float bh_n = bhh[d*384 + 256 + j];
    __syncthreads();

    #define PREFETCH(TT) do {                                                        \
        _Pragma("unroll")                                                            \
        for (int r_ = 0; r_ < 3; r_++) {                                             \
            int u_ = tid + 512*r_;                                                   \
            int i_ = u_ / 96, c_ = u_ % 96;                                          \
            int tk_ = tok[(size_t)(s*64 + (TT))*64 + bc*16 + i_];                    \
            const float4* src_ = (const float4*)(g_vg + (size_t)tk_*768 + d*384) + c_;\
            uint32_t da_ = (uint32_t)__cvta_generic_to_shared(&xg[i_][c_*4]);        \
            asm volatile("cp.async.cg.shared.global [%0], [%1], 16;"                 \
                         :: "r"(da_), "l"(src_));                                    \
        }                                                                            \
        asm volatile("cp.async.commit_group;");                                      \
    } while (0)

    PREFETCH(d ? 63 : 0);
    for (int t = 0; t < 64; t++) {
        const int tt = d ? 63 - t : t;
        ull a[12];
#pragma unroll
        for (int i = 0; i < 12; i++) a[i] = 0ull;
#pragma unroll 1
        for (int q = 0; q < 32; q++) {
            ulonglong2 wr = wp[q*384 + j];
            ulonglong2 wz = wp[q*384 + 128 + j];
            ulonglong2 wn = wp[q*384 + 256 + j];
#pragma unroll
            for (int i = 0; i < 4; i++) {
                ulonglong2 x = ((const ulonglong2*)hsm[rg*4 + i])[q];
                a[3*i+0] = ff2(x.x, wr.x, a[3*i+0]);
                a[3*i+0] = ff2(x.y, wr.y, a[3*i+0]);
                a[3*i+1] = ff2(x.x, wz.x, a[3*i+1]);
                a[3*i+1] = ff2(x.y, wz.y, a[3*i+1]);
                a[3*i+2] = ff2(x.x, wn.x, a[3*i+2]);
                a[3*i+2] = ff2(x.y, wn.y, a[3*i+2]);
            }
        }
        asm volatile("cp.async.wait_group 0;");
        __syncthreads();
#pragma unroll
        for (int i = 0; i < 4; i++) {
            const int row = rg*4 + i;
            float2 fr = up2(a[3*i+0]);
            float2 fz = up2(a[3*i+1]);
            float2 fn = up2(a[3*i+2]);
            float r = sigm(xg[row][j]       + fr.x + fr.y + bh_r);
            float z = sigm(xg[row][128 + j] + fz.x + fz.y + bh_z);
            float n = tanha(xg[row][256 + j] + r * (fn.x + fn.y + bh_n));
            float hp = hsm[row][j];
            float hn = (1.f - z) * n + z * hp;
            hsm[row][j] = hn;
            g_out1[((size_t)(s*64 + tt)*64 + bc*16 + row)*256 + d*128 + j] = hn;
        }
        __syncthreads();
        if (t + 1 < 64) PREFETCH(d ? 63 - (t+1) : t+1);
    }
    #undef PREFETCH
}

// ---------------- K3/K8: attention score = proj . tanh(x @ W + b), fused ----------------
// block = 16 rows, 256 threads = (k<128, rg<2). Thread: cols k, k+128 x 8 rows.
// q-loop unrolled x2 to amortize address ALU.  (R13 version — measured best)
__global__ void __launch_bounds__(256, 3) k_score(int level, const float* __restrict__ bias,
                                                  const float* __restrict__ proj) {
    __shared__ __align__(16) float xs[16][256];
    __shared__ float red[16][4];
    const float* x       = level ? g_out2 : g_out1;
    const ulonglong2* wp = level ? g_WW2p : g_WW1p;
    float* out           = level ? g_scores2 : g_scores1;
    const int rb = blockIdx.x, tid = threadIdx.x;
    const int k = tid & 127, rg = tid >> 7;
    for (int u = tid; u < 16*64; u += 256) {
        int i = u >> 6, f = u & 63;
        ((float4*)xs[i])[f] = ((const float4*)x)[(size_t)(rb*16 + i)*64 + f];
    }
    __syncthreads();
    ull acc[16];
#pragma unroll
    for (int i = 0; i < 16; i++) acc[i] = 0ull;
#pragma unroll 2
    for (int q = 0; q < 64; q++) {
        ulonglong2 w0 = wp[q*256 + k];
        ulonglong2 w1 = wp[q*256 + 128 + k];
#pragma unroll
        for (int i = 0; i < 8; i++) {
            ulonglong2 xv = ((const ulonglong2*)xs[rg*8 + i])[q];
            acc[2*i]   = ff2(xv.x, w0.x, acc[2*i]);
            acc[2*i]   = ff2(xv.y, w0.y, acc[2*i]);
            acc[2*i+1] = ff2(xv.x, w1.x, acc[2*i+1]);
            acc[2*i+1] = ff2(xv.y, w1.y, acc[2*i+1]);
        }
    }
    const float b0 = bias[k], b1 = bias[128 + k];
    const float p0 = proj[k], p1 = proj[128 + k];
    const int lane = tid & 31, wrp4 = (tid >> 5) & 3;
#pragma unroll 1
    for (int i = 0; i < 8; i++) {
        float2 f0 = up2(acc[2*i]);
        float2 f1 = up2(acc[2*i+1]);
        float v = tanha(f0.x + f0.y + b0) * p0 + tanha(f1.x + f1.y + b1) * p1;
#pragma unroll
        for (int o = 16; o > 0; o >>= 1) v += __shfl_xor_sync(0xffffffffu, v, o);
        if (lane == 0) red[rg*8 + i][wrp4] = v;
    }
    __syncthreads();
    if (tid < 16) {
        float sm = red[tid][0] + red[tid][1] + red[tid][2] + red[tid][3];
        out[rb*16 + tid] = sm;
    }
}

// ---------------- K4: softmax over tokens ----------------
__global__ void k_softmax() {
    const int s = blockIdx.x, b = threadIdx.x;
    const float* sc = g_scores1 + (size_t)s*64*64 + b;
    float m = -1e30f;
    for (int t = 0; t < 64; t++) m = fmaxf(m, sc[(size_t)t*64]);
    float sum = 0.f;
    for (int t = 0; t < 64; t++) sum += __expf(sc[(size_t)t*64] - m);
    float inv = __fdividef(1.f, sum);
    float* al = g_alpha1 + (size_t)s*64*64 + b;
    for (int t = 0; t < 64; t++) al[(size_t)t*64] = __expf(sc[(size_t)t*64] - m) * inv;
}

// ---------------- K5: sentence vectors ----------------
__global__ void k_sent() {
    const int blk = blockIdx.x, s = blk >> 6, b = blk & 63, h = threadIdx.x;
    float acc = 0.f;
    for (int t = 0; t < 64; t++) {
        float a = g_alpha1[(size_t)(s*64 + t)*64 + b];
        acc += a * g_out1[((size_t)(s*64 + t)*64 + b)*256 + h];
    }
    g_sent[(size_t)(s*64 + b)*256 + h] = acc;
}

// ---------------- K6: input-gate GEMM (inter), K=256 ----------------
__global__ void __launch_bounds__(384) k_xg2(const float* __restrict__ bih2) {
    __shared__ __align__(16) float xs[16][256];
    const int rb = blockIdx.x, d = blockIdx.y, tid = threadIdx.x;
    for (int u = tid; u < 16*64; u += 384) {
        int i = u >> 6, f = u & 63;
        ((float4*)xs[i])[f] = ((const float4*)g_sent)[(size_t)(rb*16 + i)*64 + f];
    }
    __syncthreads();
    const int g2 = tid % 192, rg = tid / 192;
    ull acc[16];
#pragma unroll
    for (int i = 0; i < 16; i++) acc[i] = 0ull;
    const ulonglong2* wp = g_Wih2p + d*(64*384);
#pragma unroll 1
    for (int q = 0; q < 64; q++) {
        ulonglong2 w0 = wp[q*384 + g2];
        ulonglong2 w1 = wp[q*384 + 192 + g2];
#pragma unroll
        for (int i = 0; i < 8; i++) {
            ulonglong2 x = ((const ulonglong2*)xs[rg*8 + i])[q];
            acc[2*i]   = ff2(x.x, w0.x, acc[2*i]);
            acc[2*i]   = ff2(x.y, w0.y, acc[2*i]);
            acc[2*i+1] = ff2(x.x, w1.x, acc[2*i+1]);
            acc[2*i+1] = ff2(x.y, w1.y, acc[2*i+1]);
        }
    }
    const float b0 = bih2[d*384 + g2], b1 = bih2[d*384 + 192 + g2];
#pragma unroll
    for (int i = 0; i < 8; i++) {
        float2 f0 = up2(acc[2*i]);
        float2 f1 = up2(acc[2*i+1]);
        float* op = g_xg2 + ((size_t)d*NROWS2 + rb*16 + rg*8 + i)*384;
        op[g2]       = f0.x + f0.y + b0;
        op[192 + g2] = f1.x + f1.y + b1;
    }
}

// ---------------- K7: inter biGRU (32 steps, BCHUNK=4) ----------------
__global__ void __launch_bounds__(384, 2) k_gru2(const float* __restrict__ bhh2) {
    __shared__ __align__(16) float hsm[4][128];
    __shared__ float ghs[4][384];
    const int bc = blockIdx.x, d = blockIdx.y, tid = threadIdx.x;
    for (int u = tid; u < 4*128; u += 384) ((float*)hsm)[u] = 0.f;
    const float bh = bhh2[d*384 + tid];
    const ulonglong2* wp = g_Whh2p + d*(32*384);
    __syncthreads();
    for (int t = 0; t < 32; t++) {
        const int tt = d ? (31 - t) : t;
        {
            const int g = tid;
            ull acc[4];
#pragma unroll
            for (int i = 0; i < 4; i++) acc[i] = 0ull;
#pragma unroll 1
            for (int q = 0; q < 32; q++) {
                ulonglong2 w = wp[q*384 + g];
#pragma unroll
                for (int i = 0; i < 4; i++) {
                    ulonglong2 x = ((const ulonglong2*)hsm[i])[q];
                    acc[i] = ff2(x.x, w.x, acc[i]);
                    acc[i] = ff2(x.y, w.y, acc[i]);
                }
            }
#pragma unroll
            for (int i = 0; i < 4; i++) {
                float2 f = up2(acc[i]);
                ghs[i][g] = f.x + f.y + bh;
            }
        }
        __syncthreads();
        if (tid < 128) {
            const int j = tid;
#pragma unroll 1
            for (int i = 0; i < 4; i++) {
                const int b = bc*4 + i;
                const float* xr = g_xg2 + ((size_t)d*NROWS2 + (size_t)tt*64 + b)*384;
                float r = sigm(xr[j]       + ghs[i][j]);
                float z = sigm(xr[128 + j] + ghs[i][128 + j]);
                float n = tanha(xr[256 + j] + r * ghs[i][256 + j]);
                float hp = hsm[i][j];
                float hn = (1.f - z) * n + z * hp;
                hsm[i][j] = hn;
                g_out2[((size_t)tt*64 + b)*256 + d*128 + j] = hn;
            }
        }
        __syncthreads();
    }
}

// ---------------- K9: doc vector ----------------
__global__ void k_doc() {
    const int b = blockIdx.x, h = threadIdx.x;
    float acc = 0.f;
    for (int s = 0; s < 32; s++)
        acc += g_scores2[s*64 + b] * g_out2[((size_t)(s*64 + b))*256 + h];
    g_doc[b*256 + h] = acc;
}

// ---------------- K10: final linear [64,5] ----------------
__global__ void k_final(const float* __restrict__ Wf, const float* __restrict__ bf,
                        float* __restrict__ out) {
    const int tid = threadIdx.x;
    if (tid >= 320) return;
    const int b = tid / 5, c = tid % 5;
    float acc = bf[c];
    for (int h = 0; h < 256; h++) acc += g_doc[b*256 + h] * Wf[c*256 + h];
    out[b*5 + c] = acc;
}

// ---------------- launch ----------------
extern "C" void kernel_launch(void* const* d_in, const int* in_sizes, int n_in,
                              void* d_out, int out_size) {
    const int*   tokens = (const int*)  d_in[0];
    const float* emb    = (const float*)d_in[1];
    const float* Wih1   = (const float*)d_in[2];
    const float* Whh1   = (const float*)d_in[3];
    const float* bih1   = (const float*)d_in[4];
    const float* bhh1   = (const float*)d_in[5];
    const float* WW1    = (const float*)d_in[6];
    const float* b1     = (const float*)d_in[7];
    const float* p1     = (const float*)d_in[8];
    const float* Wih2   = (const float*)d_in[9];
    const float* Whh2   = (const float*)d_in[10];
    const float* bih2   = (const float*)d_in[11];
    const float* bhh2   = (const float*)d_in[12];
    const float* WW2    = (const float*)d_in[13];
    const float* b2     = (const float*)d_in[14];
    const float* p2     = (const float*)d_in[15];
    const float* Wf     = (const float*)d_in[16];
    const float* bf     = (const float*)d_in[17];
    float* out = (float*)d_out;

    k_pack   <<<152, 256>>>(Wih1, Whh1, WW1, Wih2, Whh2, WW2);
    k_vg     <<<2000, 768>>>(emb, bih1);
    k_gru1   <<<dim3(4, 2, 32), 512>>>(bhh1, tokens);
    k_score  <<<8192, 256>>>(0, b1, p1);
    k_softmax<<<32, 64>>>();
    k_sent   <<<2048, 256>>>();
    k_xg2    <<<dim3(128, 2), 384>>>(bih2);
    k_gru2   <<<dim3(16, 2), 384>>>(bhh2);
    k_score  <<<128, 256>>>(1, b2, p2);
    k_doc    <<<64, 256>>>();
    k_final  <<<1, 512>>>(Wf, bf, out);
}

// round 16
// speedup vs baseline: 1.2408x; 1.1079x over previous
#include <cuda_runtime.h>
#include <cstdint>

typedef unsigned long long ull;

// ---------------- problem constants ----------------
#define NS 32
#define NT 64
#define NB 64
#define NROWS1 (NS*NT*NB)   // 131072
#define NROWS2 (NS*NB)      // 2048
#define NV 32000

// ---------------- scratch (device globals) ----------------
__device__ ulonglong2 g_Wih1p[2*32*384];   // [d][q<32][g]: k-pairs of Wih_intra
__device__ ulonglong2 g_Whh1p[2*32*384];
__device__ ulonglong2 g_Wih2p[2*64*384];
__device__ ulonglong2 g_Whh2p[2*32*384];

// tf32 hi/lo split of W_W (levels 1,2): layout [kc<32][hl<2][n<256][c<4] float2
__device__ float2 g_WW1t[32*2*256*4];
__device__ float2 g_WW2t[32*2*256*4];

__device__ float g_vg    [(size_t)NV*768];  // vocab input-gates: [v][d*384+g]
__device__ float g_out1  [(size_t)NROWS1*256];
__device__ float g_scores1[NROWS1];
__device__ float g_alpha1 [NROWS1];
__device__ float g_sent  [NROWS2*256];
__device__ float g_xg2   [2*NROWS2*384];
__device__ float g_out2  [NROWS2*256];
__device__ float g_scores2[NROWS2];
__device__ float g_doc   [NB*256];

// ---------------- helpers ----------------
__device__ __forceinline__ ull ff2(ull a, ull b, ull c) {
    ull d;
    asm("fma.rn.f32x2 %0, %1, %2, %3;" : "=l"(d) : "l"(a), "l"(b), "l"(c));
    return d;
}
__device__ __forceinline__ float2 up2(ull v) {
    float2 f;
    asm("mov.b64 {%0, %1}, %2;" : "=f"(f.x), "=f"(f.y) : "l"(v));
    return f;
}
__device__ __forceinline__ float sigm(float x) {
    return __fdividef(1.f, 1.f + __expf(-x));
}
__device__ __forceinline__ float tanha(float x) {
    float ax = fabsf(x);
    float e  = __expf(-2.f * ax);
    float t  = (1.f - e) * __fdividef(1.f, 1.f + e);
    return copysignf(t, x);
}
__device__ __forceinline__ unsigned tf32u(float x) {
    unsigned u;
    asm("cvt.rna.tf32.f32 %0, %1;" : "=r"(u) : "f"(x));
    return u;
}
__device__ __forceinline__ void mma8(float* c, const unsigned* a, unsigned b0, unsigned b1) {
    asm("mma.sync.aligned.m16n8k8.row.col.f32.tf32.tf32.f32 "
        "{%0,%1,%2,%3},{%4,%5,%6,%7},{%8,%9},{%0,%1,%2,%3};"
        : "+f"(c[0]), "+f"(c[1]), "+f"(c[2]), "+f"(c[3])
        : "r"(a[0]), "r"(a[1]), "r"(a[2]), "r"(a[3]), "r"(b0), "r"(b1));
}

// ---------------- K0: pack GRU weights into k-pair (f32x2) layouts ----------------
__global__ void k_pack(const float* __restrict__ Wih1, const float* __restrict__ Whh1,
                       const float* __restrict__ Wih2, const float* __restrict__ Whh2) {
    const int total = 24576 + 24576 + 49152 + 24576;
    for (int n = blockIdx.x * blockDim.x + threadIdx.x; n < total; n += gridDim.x * blockDim.x) {
        int m = n;
        if (m < 24576) {
            int d = m / (32*384), r = m % (32*384), q = r / 384, g = r % 384;
            const float* w = Wih1 + (d*384 + g)*128 + 4*q;
            ((float4*)g_Wih1p)[m] = make_float4(w[0], w[1], w[2], w[3]);
            continue;
        } m -= 24576;
        if (m < 24576) {
            int d = m / (32*384), r = m % (32*384), q = r / 384, g = r % 384;
            const float* w = Whh1 + (d*384 + g)*128 + 4*q;
            ((float4*)g_Whh1p)[m] = make_float4(w[0], w[1], w[2], w[3]);
            continue;
        } m -= 24576;
        if (m < 49152) {
            int d = m / (64*384), r = m % (64*384), q = r / 384, g = r % 384;
            const float* w = Wih2 + (d*384 + g)*256 + 4*q;
            ((float4*)g_Wih2p)[m] = make_float4(w[0], w[1], w[2], w[3]);
            continue;
        } m -= 49152;
        {
            int d = m / (32*384), r = m % (32*384), q = r / 384, g = r % 384;
            const float* w = Whh2 + (d*384 + g)*128 + 4*q;
            ((float4*)g_Whh2p)[m] = make_float4(w[0], w[1], w[2], w[3]);
        }
    }
}

// ---------------- K0b: split W_W into tf32 hi/lo staged layout ----------------
// entry [l<2][kc<32][n<256][c<4]: pairs {B[kc*8+c][n], B[kc*8+c+4][n]} as tf32 hi & lo.
__global__ void k_packtf(const float* __restrict__ WW1, const float* __restrict__ WW2) {
    int idx = blockIdx.x * blockDim.x + threadIdx.x;
    if (idx >= 2*32*256*4) return;
    int c = idx & 3, n = (idx >> 2) & 255, kc = (idx >> 10) & 31, l = idx >> 15;
    const float* W = l ? WW2 : WW1;
    float2* dst = l ? g_WW2t : g_WW1t;
    int k0 = kc*8 + c, k1 = k0 + 4;
    float v0 = W[k0*256 + n], v1 = W[k1*256 + n];
    unsigned h0 = tf32u(v0), h1 = tf32u(v1);
    float f0 = __uint_as_float(h0), f1 = __uint_as_float(h1);
    dst[(kc*2 + 0)*1024 + n*4 + c] = make_float2(f0, f1);
    dst[(kc*2 + 1)*1024 + n*4 + c] =
        make_float2(__uint_as_float(tf32u(v0 - f0)), __uint_as_float(tf32u(v1 - f1)));
}

// ---------------- K1: vocab input-gate table: vg[v] = embed[v] @ Wih^T + bih ----------------
__global__ void __launch_bounds__(768) k_vg(const float* __restrict__ emb,
                                            const float* __restrict__ bih) {
    __shared__ __align__(16) float xs[16][128];
    const int rb = blockIdx.x, tid = threadIdx.x;
    if (tid < 512) {
        int i = tid >> 5, f = tid & 31;
        ((float4*)xs[i])[f] = ((const float4*)emb)[(size_t)(rb*16 + i)*32 + f];
    }
    __syncthreads();
    const int g = tid % 384, rg = tid / 384;    // rows rg*8 .. rg*8+7
    ull acc[16];
#pragma unroll
    for (int i = 0; i < 16; i++) acc[i] = 0ull;
#pragma unroll 1
    for (int q = 0; q < 32; q++) {
        ulonglong2 w0 = g_Wih1p[q*384 + g];
        ulonglong2 w1 = g_Wih1p[32*384 + q*384 + g];
#pragma unroll
        for (int i = 0; i < 8; i++) {
            ulonglong2 x = ((const ulonglong2*)xs[rg*8 + i])[q];
            acc[2*i]   = ff2(x.x, w0.x, acc[2*i]);
            acc[2*i]   = ff2(x.y, w0.y, acc[2*i]);
            acc[2*i+1] = ff2(x.x, w1.x, acc[2*i+1]);
            acc[2*i+1] = ff2(x.y, w1.y, acc[2*i+1]);
        }
    }
    const float b0 = bih[g], b1 = bih[384 + g];
#pragma unroll
    for (int i = 0; i < 8; i++) {
        float2 f0 = up2(acc[2*i]);
        float2 f1 = up2(acc[2*i+1]);
        size_t v = (size_t)(rb*16 + rg*8 + i);
        g_vg[v*768 + g]       = f0.x + f0.y + b0;
        g_vg[v*768 + 384 + g] = f1.x + f1.y + b1;
    }
}

// ---------------- K2: intra biGRU (R11 measured-best version) ----------------
__global__ void __launch_bounds__(512, 2) k_gru1(const float* __restrict__ bhh,
                                                 const int* __restrict__ tok) {
    __shared__ __align__(16) float hsm[16][128];
    __shared__ __align__(16) float xg[16][384];
    const int bc = blockIdx.x, d = blockIdx.y, s = blockIdx.z, tid = threadIdx.x;
    const int j = tid & 127, rg = tid >> 7;      // rows rg*4 .. rg*4+3
    for (int u = tid; u < 16*128; u += 512) ((float*)hsm)[u] = 0.f;
    const ulonglong2* wp = g_Whh1p + d*(32*384);
    const float bh_r = bhh[d*384 + j];
    const float bh_z = bhh[d*384 + 128 + j];
    const float bh_n = bhh[d*384 + 256 + j];
    __syncthreads();

    #define PREFETCH(TT) do {                                                        \
        _Pragma("unroll")                                                            \
        for (int r_ = 0; r_ < 3; r_++) {                                             \
            int u_ = tid + 512*r_;                                                   \
            int i_ = u_ / 96, c_ = u_ % 96;                                          \
            int tk_ = tok[(size_t)(s*64 + (TT))*64 + bc*16 + i_];                    \
            const float4* src_ = (const float4*)(g_vg + (size_t)tk_*768 + d*384) + c_;\
            uint32_t da_ = (uint32_t)__cvta_generic_to_shared(&xg[i_][c_*4]);        \
            asm volatile("cp.async.cg.shared.global [%0], [%1], 16;"                 \
                         :: "r"(da_), "l"(src_));                                    \
        }                                                                            \
        asm volatile("cp.async.commit_group;");                                      \
    } while (0)

    PREFETCH(d ? 63 : 0);
    for (int t = 0; t < 64; t++) {
        const int tt = d ? 63 - t : t;
        ull a[12];
#pragma unroll
        for (int i = 0; i < 12; i++) a[i] = 0ull;
#pragma unroll 1
        for (int q = 0; q < 32; q++) {
            ulonglong2 wr = wp[q*384 + j];
            ulonglong2 wz = wp[q*384 + 128 + j];
            ulonglong2 wn = wp[q*384 + 256 + j];
#pragma unroll
            for (int i = 0; i < 4; i++) {
                ulonglong2 x = ((const ulonglong2*)hsm[rg*4 + i])[q];
                a[3*i+0] = ff2(x.x, wr.x, a[3*i+0]);
                a[3*i+0] = ff2(x.y, wr.y, a[3*i+0]);
                a[3*i+1] = ff2(x.x, wz.x, a[3*i+1]);
                a[3*i+1] = ff2(x.y, wz.y, a[3*i+1]);
                a[3*i+2] = ff2(x.x, wn.x, a[3*i+2]);
                a[3*i+2] = ff2(x.y, wn.y, a[3*i+2]);
            }
        }
        asm volatile("cp.async.wait_group 0;");
        __syncthreads();
#pragma unroll
        for (int i = 0; i < 4; i++) {
            const int row = rg*4 + i;
            float2 fr = up2(a[3*i+0]);
            float2 fz = up2(a[3*i+1]);
            float2 fn = up2(a[3*i+2]);
            float r = sigm(xg[row][j]       + fr.x + fr.y + bh_r);
            float z = sigm(xg[row][128 + j] + fz.x + fz.y + bh_z);
            float n = tanha(xg[row][256 + j] + r * (fn.x + fn.y + bh_n));
            float hp = hsm[row][j];
            float hn = (1.f - z) * n + z * hp;
            hsm[row][j] = hn;
            g_out1[((size_t)(s*64 + tt)*64 + bc*16 + row)*256 + d*128 + j] = hn;
        }
        __syncthreads();
        if (t + 1 < 64) PREFETCH(d ? 63 - (t+1) : t+1);
    }
    #undef PREFETCH
}

// ---------------- K3/K8: attention score via tf32 mma (3xTF32 split) ----------------
// block = 64 rows, 256 threads (8 warps). Warp w: m-tile w/2 (16 rows), cols (w&1)*128 + 16 n-tiles.
// K=256 in 32 chunks of 8; W hi/lo staged into smem via cp.async double buffer.
__global__ void __launch_bounds__(256) k_score_mma(int level, const float* __restrict__ bias,
                                                   const float* __restrict__ proj) {
    extern __shared__ __align__(16) float smem[];
    float2* sB   = (float2*)smem;            // [buf<2][hl<2][n<256][c<4] float2 = 32 KB
    float*  xs   = smem + 8192;              // 64 rows x 260 (padded) = 66560 B
    float*  sbias = xs + 64*260;
    float*  sproj = sbias + 256;
    float*  red   = sproj + 256;             // [64][2]

    const float*  x   = level ? g_out2 : g_out1;
    const float2* Bt  = level ? g_WW2t : g_WW1t;
    float*        out = level ? g_scores2 : g_scores1;
    const int rb = blockIdx.x, tid = threadIdx.x;
    const int w = tid >> 5, lane = tid & 31;
    const int gid = lane >> 2, tig = lane & 3;
    const int mt = w >> 1;
    const int nbase = (w & 1) * 128;

    sbias[tid] = bias[tid];
    sproj[tid] = proj[tid];

    // xs: 64 rows x 64 float4 via cp.async (group 1)
    for (int u = tid; u < 64*64; u += 256) {
        int i = u >> 6, f = u & 63;
        uint32_t da = (uint32_t)__cvta_generic_to_shared(&xs[i*260 + f*4]);
        const float4* src = ((const float4*)x) + (size_t)(rb*64 + i)*64 + f;
        asm volatile("cp.async.cg.shared.global [%0], [%1], 16;" :: "r"(da), "l"(src));
    }
    asm volatile("cp.async.commit_group;");

    #define STAGEB(KC, BUF) do {                                                     \
        const float2* sb_ = Bt + (KC)*2048;                                          \
        _Pragma("unroll")                                                            \
        for (int r_ = 0; r_ < 4; r_++) {                                             \
            int i_ = tid + 256*r_;                                                   \
            uint32_t da_ = (uint32_t)__cvta_generic_to_shared(sB + (BUF)*2048 + i_*2);\
            asm volatile("cp.async.cg.shared.global [%0], [%1], 16;"                 \
                         :: "r"(da_), "l"(sb_ + i_*2));                              \
        }                                                                            \
        asm volatile("cp.async.commit_group;");                                      \
    } while (0)

    STAGEB(0, 0);

    float c[16][4];
#pragma unroll
    for (int i = 0; i < 16; i++)
#pragma unroll
        for (int e = 0; e < 4; e++) c[i][e] = 0.f;

#pragma unroll 1
    for (int kc = 0; kc < 32; kc++) {
        const int cur = kc & 1;
        if (kc + 1 < 32) {
            STAGEB(kc + 1, (kc + 1) & 1);
            asm volatile("cp.async.wait_group 1;");
        } else {
            asm volatile("cp.async.wait_group 0;");
        }
        __syncthreads();

        // A fragments (hi + lo) for this k-chunk
        const float* xr = xs + (mt*16 + gid)*260 + kc*8 + tig;
        float x0 = xr[0], x1 = xr[8*260], x2 = xr[4], x3 = xr[8*260 + 4];
        unsigned ah[4], al[4];
        ah[0] = tf32u(x0); ah[1] = tf32u(x1); ah[2] = tf32u(x2); ah[3] = tf32u(x3);
        al[0] = tf32u(x0 - __uint_as_float(ah[0]));
        al[1] = tf32u(x1 - __uint_as_float(ah[1]));
        al[2] = tf32u(x2 - __uint_as_float(ah[2]));
        al[3] = tf32u(x3 - __uint_as_float(ah[3]));

        const float2* bh = sB + (cur*2 + 0)*1024 + gid*4 + tig;
        const float2* bl = sB + (cur*2 + 1)*1024 + gid*4 + tig;
#pragma unroll
        for (int nt = 0; nt < 16; nt++) {
            const int off = nbase*4 + nt*32;
            float2 h  = bh[off];
            float2 lo = bl[off];
            unsigned b0 = __float_as_uint(h.x),  b1 = __float_as_uint(h.y);
            unsigned l0 = __float_as_uint(lo.x), l1 = __float_as_uint(lo.y);
            mma8(c[nt], ah, b0, b1);
            mma8(c[nt], al, b0, b1);
            mma8(c[nt], ah, l0, l1);
        }
        __syncthreads();
    }
    #undef STAGEB

    // epilogue: tanh*proj, reduce over cols
    float s0 = 0.f, s1 = 0.f;
#pragma unroll
    for (int nt = 0; nt < 16; nt++) {
        int cn0 = nbase + nt*8 + 2*tig, cn1 = cn0 + 1;
        float b0 = sbias[cn0], b1 = sbias[cn1];
        float p0 = sproj[cn0], p1 = sproj[cn1];
        s0 += tanha(c[nt][0] + b0)*p0 + tanha(c[nt][1] + b1)*p1;
        s1 += tanha(c[nt][2] + b0)*p0 + tanha(c[nt][3] + b1)*p1;
    }
    s0 += __shfl_xor_sync(0xffffffffu, s0, 1);
    s0 += __shfl_xor_sync(0xffffffffu, s0, 2);
    s1 += __shfl_xor_sync(0xffffffffu, s1, 1);
    s1 += __shfl_xor_sync(0xffffffffu, s1, 2);
    if (tig == 0) {
        red[(mt*16 + gid)*2 + (w & 1)]     = s0;
        red[(mt*16 + gid + 8)*2 + (w & 1)] = s1;
    }
    __syncthreads();
    if (tid < 64) out[rb*64 + tid] = red[tid*2] + red[tid*2 + 1];
}

// ---------------- K4: softmax over tokens ----------------
__global__ void k_softmax() {
    const int s = blockIdx.x, b = threadIdx.x;
    const float* sc = g_scores1 + (size_t)s*64*64 + b;
    float m = -1e30f;
    for (int t = 0; t < 64; t++) m = fmaxf(m, sc[(size_t)t*64]);
    float sum = 0.f;
    for (int t = 0; t < 64; t++) sum += __expf(sc[(size_t)t*64] - m);
    float inv = __fdividef(1.f, sum);
    float* al = g_alpha1 + (size_t)s*64*64 + b;
    for (int t = 0; t < 64; t++) al[(size_t)t*64] = __expf(sc[(size_t)t*64] - m) * inv;
}

// ---------------- K5: sentence vectors ----------------
__global__ void k_sent() {
    const int blk = blockIdx.x, s = blk >> 6, b = blk & 63, h = threadIdx.x;
    float acc = 0.f;
    for (int t = 0; t < 64; t++) {
        float a = g_alpha1[(size_t)(s*64 + t)*64 + b];
        acc += a * g_out1[((size_t)(s*64 + t)*64 + b)*256 + h];
    }
    g_sent[(size_t)(s*64 + b)*256 + h] = acc;
}

// ---------------- K6: input-gate GEMM (inter), K=256 ----------------
__global__ void __launch_bounds__(384) k_xg2(const float* __restrict__ bih2) {
    __shared__ __align__(16) float xs[16][256];
    const int rb = blockIdx.x, d = blockIdx.y, tid = threadIdx.x;
    for (int u = tid; u < 16*64; u += 384) {
        int i = u >> 6, f = u & 63;
        ((float4*)xs[i])[f] = ((const float4*)g_sent)[(size_t)(rb*16 + i)*64 + f];
    }
    __syncthreads();
    const int g2 = tid % 192, rg = tid / 192;
    ull acc[16];
#pragma unroll
    for (int i = 0; i < 16; i++) acc[i] = 0ull;
    const ulonglong2* wp = g_Wih2p + d*(64*384);
#pragma unroll 1
    for (int q = 0; q < 64; q++) {
        ulonglong2 w0 = wp[q*384 + g2];
        ulonglong2 w1 = wp[q*384 + 192 + g2];
#pragma unroll
        for (int i = 0; i < 8; i++) {
            ulonglong2 x = ((const ulonglong2*)xs[rg*8 + i])[q];
            acc[2*i]   = ff2(x.x, w0.x, acc[2*i]);
            acc[2*i]   = ff2(x.y, w0.y, acc[2*i]);
            acc[2*i+1] = ff2(x.x, w1.x, acc[2*i+1]);
            acc[2*i+1] = ff2(x.y, w1.y, acc[2*i+1]);
        }
    }
    const float b0 = bih2[d*384 + g2], b1 = bih2[d*384 + 192 + g2];
#pragma unroll
    for (int i = 0; i < 8; i++) {
        float2 f0 = up2(acc[2*i]);
        float2 f1 = up2(acc[2*i+1]);
        float* op = g_xg2 + ((size_t)d*NROWS2 + rb*16 + rg*8 + i)*384;
        op[g2]       = f0.x + f0.y + b0;
        op[192 + g2] = f1.x + f1.y + b1;
    }
}

// ---------------- K7: inter biGRU (32 steps, BCHUNK=4) ----------------
__global__ void __launch_bounds__(384, 2) k_gru2(const float* __restrict__ bhh2) {
    __shared__ __align__(16) float hsm[4][128];
    __shared__ float ghs[4][384];
    const int bc = blockIdx.x, d = blockIdx.y, tid = threadIdx.x;
    for (int u = tid; u < 4*128; u += 384) ((float*)hsm)[u] = 0.f;
    const float bh = bhh2[d*384 + tid];
    const ulonglong2* wp = g_Whh2p + d*(32*384);
    __syncthreads();
    for (int t = 0; t < 32; t++) {
        const int tt = d ? (31 - t) : t;
        {
            const int g = tid;
            ull acc[4];
#pragma unroll
            for (int i = 0; i < 4; i++) acc[i] = 0ull;
#pragma unroll 1
            for (int q = 0; q < 32; q++) {
                ulonglong2 w = wp[q*384 + g];
#pragma unroll
                for (int i = 0; i < 4; i++) {
                    ulonglong2 x = ((const ulonglong2*)hsm[i])[q];
                    acc[i] = ff2(x.x, w.x, acc[i]);
                    acc[i] = ff2(x.y, w.y, acc[i]);
                }
            }
#pragma unroll
            for (int i = 0; i < 4; i++) {
                float2 f = up2(acc[i]);
                ghs[i][g] = f.x + f.y + bh;
            }
        }
        __syncthreads();
        if (tid < 128) {
            const int j = tid;
#pragma unroll 1
            for (int i = 0; i < 4; i++) {
                const int b = bc*4 + i;
                const float* xr = g_xg2 + ((size_t)d*NROWS2 + (size_t)tt*64 + b)*384;
                float r = sigm(xr[j]       + ghs[i][j]);
                float z = sigm(xr[128 + j] + ghs[i][128 + j]);
                float n = tanha(xr[256 + j] + r * ghs[i][256 + j]);
                float hp = hsm[i][j];
                float hn = (1.f - z) * n + z * hp;
                hsm[i][j] = hn;
                g_out2[((size_t)tt*64 + b)*256 + d*128 + j] = hn;
            }
        }
        __syncthreads();
    }
}

// ---------------- K9: doc vector ----------------
__global__ void k_doc() {
    const int b = blockIdx.x, h = threadIdx.x;
    float acc = 0.f;
    for (int s = 0; s < 32; s++)
        acc += g_scores2[s*64 + b] * g_out2[((size_t)(s*64 + b))*256 + h];
    g_doc[b*256 + h] = acc;
}

// ---------------- K10: final linear [64,5] ----------------
__global__ void k_final(const float* __restrict__ Wf, const float* __restrict__ bf,
                        float* __restrict__ out) {
    const int tid = threadIdx.x;
    if (tid >= 320) return;
    const int b = tid / 5, c = tid % 5;
    float acc = bf[c];
    for (int h = 0; h < 256; h++) acc += g_doc[b*256 + h] * Wf[c*256 + h];
    out[b*5 + c] = acc;
}

// ---------------- launch ----------------
extern "C" void kernel_launch(void* const* d_in, const int* in_sizes, int n_in,
                              void* d_out, int out_size) {
    const int*   tokens = (const int*)  d_in[0];
    const float* emb    = (const float*)d_in[1];
    const float* Wih1   = (const float*)d_in[2];
    const float* Whh1   = (const float*)d_in[3];
    const float* bih1   = (const float*)d_in[4];
    const float* bhh1   = (const float*)d_in[5];
    const float* WW1    = (const float*)d_in[6];
    const float* b1     = (const float*)d_in[7];
    const float* p1     = (const float*)d_in[8];
    const float* Wih2   = (const float*)d_in[9];
    const float* Whh2   = (const float*)d_in[10];
    const float* bih2   = (const float*)d_in[11];
    const float* bhh2   = (const float*)d_in[12];
    const float* WW2    = (const float*)d_in[13];
    const float* b2     = (const float*)d_in[14];
    const float* p2     = (const float*)d_in[15];
    const float* Wf     = (const float*)d_in[16];
    const float* bf     = (const float*)d_in[17];
    float* out = (float*)d_out;

    static int smem_set = 0;
    if (!smem_set) {
        cudaFuncSetAttribute(k_score_mma, cudaFuncAttributeMaxDynamicSharedMemorySize, 101888);
        smem_set = 1;
    }

    k_pack     <<<152, 256>>>(Wih1, Whh1, Wih2, Whh2);
    k_packtf   <<<256, 256>>>(WW1, WW2);
    k_vg       <<<2000, 768>>>(emb, bih1);
    k_gru1     <<<dim3(4, 2, 32), 512>>>(bhh1, tokens);
    k_score_mma<<<2048, 256, 101888>>>(0, b1, p1);
    k_softmax  <<<32, 64>>>();
    k_sent     <<<2048, 256>>>();
    k_xg2      <<<dim3(128, 2), 384>>>(bih2);
    k_gru2     <<<dim3(16, 2), 384>>>(bhh2);
    k_score_mma<<<32, 256, 101888>>>(1, b2, p2);
    k_doc      <<<64, 256>>>();
    k_final    <<<1, 512>>>(Wf, bf, out);
}

// round 17
// speedup vs baseline: 1.2885x; 1.0384x over previous
#include <cuda_runtime.h>
#include <cstdint>

typedef unsigned long long ull;

// ---------------- problem constants ----------------
#define NS 32
#define NT 64
#define NB 64
#define NROWS1 (NS*NT*NB)   // 131072
#define NROWS2 (NS*NB)      // 2048
#define NV 32000

// ---------------- scratch (device globals) ----------------
__device__ ulonglong2 g_Wih1p[2*32*384];   // [d][q<32][g]: k-pairs of Wih_intra
__device__ ulonglong2 g_Whh1p[2*32*384];
__device__ ulonglong2 g_Wih2p[2*64*384];
__device__ ulonglong2 g_Whh2p[2*32*384];

// tf32 hi/lo split of W_W (levels 1,2): layout [kc<32][hl<2][n<256][c<4] float2
__device__ float2 g_WW1t[32*2*256*4];
__device__ float2 g_WW2t[32*2*256*4];

__device__ float g_vg    [(size_t)NV*768];  // vocab input-gates: [v][d*384+g]
__device__ float g_out1  [(size_t)NROWS1*256];
__device__ float g_scores1[NROWS1];
__device__ float g_alpha1 [NROWS1];
__device__ float g_sent  [NROWS2*256];
__device__ float g_xg2   [2*NROWS2*384];
__device__ float g_out2  [NROWS2*256];
__device__ float g_scores2[NROWS2];
__device__ float g_doc   [NB*256];

// ---------------- helpers ----------------
__device__ __forceinline__ ull ff2(ull a, ull b, ull c) {
    ull d;
    asm("fma.rn.f32x2 %0, %1, %2, %3;" : "=l"(d) : "l"(a), "l"(b), "l"(c));
    return d;
}
__device__ __forceinline__ float2 up2(ull v) {
    float2 f;
    asm("mov.b64 {%0, %1}, %2;" : "=f"(f.x), "=f"(f.y) : "l"(v));
    return f;
}
__device__ __forceinline__ float sigm(float x) {
    return __fdividef(1.f, 1.f + __expf(-x));
}
__device__ __forceinline__ float tanha(float x) {
    float ax = fabsf(x);
    float e  = __expf(-2.f * ax);
    float t  = (1.f - e) * __fdividef(1.f, 1.f + e);
    return copysignf(t, x);
}
__device__ __forceinline__ unsigned tf32u(float x) {
    unsigned u;
    asm("cvt.rna.tf32.f32 %0, %1;" : "=r"(u) : "f"(x));
    return u;
}
__device__ __forceinline__ void mma8(float* c, const unsigned* a, unsigned b0, unsigned b1) {
    asm("mma.sync.aligned.m16n8k8.row.col.f32.tf32.tf32.f32 "
        "{%0,%1,%2,%3},{%4,%5,%6,%7},{%8,%9},{%0,%1,%2,%3};"
        : "+f"(c[0]), "+f"(c[1]), "+f"(c[2]), "+f"(c[3])
        : "r"(a[0]), "r"(a[1]), "r"(a[2]), "r"(a[3]), "r"(b0), "r"(b1));
}

// ---------------- K0: pack GRU weights into k-pair (f32x2) layouts ----------------
__global__ void k_pack(const float* __restrict__ Wih1, const float* __restrict__ Whh1,
                       const float* __restrict__ Wih2, const float* __restrict__ Whh2) {
    const int total = 24576 + 24576 + 49152 + 24576;
    for (int n = blockIdx.x * blockDim.x + threadIdx.x; n < total; n += gridDim.x * blockDim.x) {
        int m = n;
        if (m < 24576) {
            int d = m / (32*384), r = m % (32*384), q = r / 384, g = r % 384;
            const float* w = Wih1 + (d*384 + g)*128 + 4*q;
            ((float4*)g_Wih1p)[m] = make_float4(w[0], w[1], w[2], w[3]);
            continue;
        } m -= 24576;
        if (m < 24576) {
            int d = m / (32*384), r = m % (32*384), q = r / 384, g = r % 384;
            const float* w = Whh1 + (d*384 + g)*128 + 4*q;
            ((float4*)g_Whh1p)[m] = make_float4(w[0], w[1], w[2], w[3]);
            continue;
        } m -= 24576;
        if (m < 49152) {
            int d = m / (64*384), r = m % (64*384), q = r / 384, g = r % 384;
            const float* w = Wih2 + (d*384 + g)*256 + 4*q;
            ((float4*)g_Wih2p)[m] = make_float4(w[0], w[1], w[2], w[3]);
            continue;
        } m -= 49152;
        {
            int d = m / (32*384), r = m % (32*384), q = r / 384, g = r % 384;
            const float* w = Whh2 + (d*384 + g)*128 + 4*q;
            ((float4*)g_Whh2p)[m] = make_float4(w[0], w[1], w[2], w[3]);
        }
    }
}

// ---------------- K0b: split W_W into tf32 hi/lo staged layout ----------------
__global__ void k_packtf(const float* __restrict__ WW1, const float* __restrict__ WW2) {
    int idx = blockIdx.x * blockDim.x + threadIdx.x;
    if (idx >= 2*32*256*4) return;
    int c = idx & 3, n = (idx >> 2) & 255, kc = (idx >> 10) & 31, l = idx >> 15;
    const float* W = l ? WW2 : WW1;
    float2* dst = l ? g_WW2t : g_WW1t;
    int k0 = kc*8 + c, k1 = k0 + 4;
    float v0 = W[k0*256 + n], v1 = W[k1*256 + n];
    unsigned h0 = tf32u(v0), h1 = tf32u(v1);
    float f0 = __uint_as_float(h0), f1 = __uint_as_float(h1);
    dst[(kc*2 + 0)*1024 + n*4 + c] = make_float2(f0, f1);
    dst[(kc*2 + 1)*1024 + n*4 + c] =
        make_float2(__uint_as_float(tf32u(v0 - f0)), __uint_as_float(tf32u(v1 - f1)));
}

// ---------------- K1: vocab input-gate table: vg[v] = embed[v] @ Wih^T + bih ----------------
__global__ void __launch_bounds__(768) k_vg(const float* __restrict__ emb,
                                            const float* __restrict__ bih) {
    __shared__ __align__(16) float xs[16][128];
    const int rb = blockIdx.x, tid = threadIdx.x;
    if (tid < 512) {
        int i = tid >> 5, f = tid & 31;
        ((float4*)xs[i])[f] = ((const float4*)emb)[(size_t)(rb*16 + i)*32 + f];
    }
    __syncthreads();
    const int g = tid % 384, rg = tid / 384;    // rows rg*8 .. rg*8+7
    ull acc[16];
#pragma unroll
    for (int i = 0; i < 16; i++) acc[i] = 0ull;
#pragma unroll 1
    for (int q = 0; q < 32; q++) {
        ulonglong2 w0 = g_Wih1p[q*384 + g];
        ulonglong2 w1 = g_Wih1p[32*384 + q*384 + g];
#pragma unroll
        for (int i = 0; i < 8; i++) {
            ulonglong2 x = ((const ulonglong2*)xs[rg*8 + i])[q];
            acc[2*i]   = ff2(x.x, w0.x, acc[2*i]);
            acc[2*i]   = ff2(x.y, w0.y, acc[2*i]);
            acc[2*i+1] = ff2(x.x, w1.x, acc[2*i+1]);
            acc[2*i+1] = ff2(x.y, w1.y, acc[2*i+1]);
        }
    }
    const float b0 = bih[g], b1 = bih[384 + g];
#pragma unroll
    for (int i = 0; i < 8; i++) {
        float2 f0 = up2(acc[2*i]);
        float2 f1 = up2(acc[2*i+1]);
        size_t v = (size_t)(rb*16 + rg*8 + i);
        g_vg[v*768 + g]       = f0.x + f0.y + b0;
        g_vg[v*768 + 384 + g] = f1.x + f1.y + b1;
    }
}

// ---------------- K2: intra biGRU, persistent per (sentence, dir, batch-chunk) ----------------
// grid (4 bc, 2 d, 32 s) = 256 blocks, 256 threads: thread = (j<128, rg<2) x 8 rows.
// Per q: 3 LDG.128 (12 wf) + 8 broadcast LDS (8 wf) vs 48 FFMA2 (24 issue-cyc) -> fma-bound.
__global__ void __launch_bounds__(256, 2) k_gru1(const float* __restrict__ bhh,
                                                 const int* __restrict__ tok) {
    __shared__ __align__(16) float hsm[16][128];
    __shared__ __align__(16) float xg[16][384];
    const int bc = blockIdx.x, d = blockIdx.y, s = blockIdx.z, tid = threadIdx.x;
    const int j = tid & 127, rg = tid >> 7;      // rows rg*8 .. rg*8+7
    for (int u = tid; u < 16*128; u += 256) ((float*)hsm)[u] = 0.f;
    const ulonglong2* wp = g_Whh1p + d*(32*384);
    const float bh_r = bhh[d*384 + j];
    const float bh_z = bhh[d*384 + 128 + j];
    const float bh_n = bhh[d*384 + 256 + j];
    __syncthreads();

    // prefetch step TT's gate rows into xg: 16 rows x 96 float4 = 1536, 6 per thread
    #define PREFETCH(TT) do {                                                        \
        _Pragma("unroll")                                                            \
        for (int r_ = 0; r_ < 6; r_++) {                                             \
            int u_ = tid + 256*r_;                                                   \
            int i_ = u_ / 96, c_ = u_ % 96;                                          \
            int tk_ = tok[(size_t)(s*64 + (TT))*64 + bc*16 + i_];                    \
            const float4* src_ = (const float4*)(g_vg + (size_t)tk_*768 + d*384) + c_;\
            uint32_t da_ = (uint32_t)__cvta_generic_to_shared(&xg[i_][c_*4]);        \
            asm volatile("cp.async.cg.shared.global [%0], [%1], 16;"                 \
                         :: "r"(da_), "l"(src_));                                    \
        }                                                                            \
        asm volatile("cp.async.commit_group;");                                      \
    } while (0)

    PREFETCH(d ? 63 : 0);
    for (int t = 0; t < 64; t++) {
        const int tt = d ? 63 - t : t;
        // ---- phase A: gh = h @ Whh^T (3 gates x 8 rows per thread) ----
        ull a[24];
#pragma unroll
        for (int i = 0; i < 24; i++) a[i] = 0ull;
        const ulonglong2* wq = wp + j;
#pragma unroll 1
        for (int q = 0; q < 32; q++) {
            ulonglong2 wr = wq[0];
            ulonglong2 wz = wq[128];
            ulonglong2 wn = wq[256];
            wq += 384;
#pragma unroll
            for (int i = 0; i < 8; i++) {
                ulonglong2 x = ((const ulonglong2*)hsm[rg*8 + i])[q];
                a[3*i+0] = ff2(x.x, wr.x, a[3*i+0]);
                a[3*i+0] = ff2(x.y, wr.y, a[3*i+0]);
                a[3*i+1] = ff2(x.x, wz.x, a[3*i+1]);
                a[3*i+1] = ff2(x.y, wz.y, a[3*i+1]);
                a[3*i+2] = ff2(x.x, wn.x, a[3*i+2]);
                a[3*i+2] = ff2(x.y, wn.y, a[3*i+2]);
            }
        }
        asm volatile("cp.async.wait_group 0;");
        __syncthreads();   // phase-A hsm reads done; xg landed
        // ---- phase B: gates + state update ----
#pragma unroll
        for (int i = 0; i < 8; i++) {
            const int row = rg*8 + i;
            float2 fr = up2(a[3*i+0]);
            float2 fz = up2(a[3*i+1]);
            float2 fn = up2(a[3*i+2]);
            float r = sigm(xg[row][j]       + fr.x + fr.y + bh_r);
            float z = sigm(xg[row][128 + j] + fz.x + fz.y + bh_z);
            float n = tanha(xg[row][256 + j] + r * (fn.x + fn.y + bh_n));
            float hp = hsm[row][j];
            float hn = (1.f - z) * n + z * hp;
            hsm[row][j] = hn;
            g_out1[((size_t)(s*64 + tt)*64 + bc*16 + row)*256 + d*128 + j] = hn;
        }
        __syncthreads();   // xg free, hsm settled
        if (t + 1 < 64) PREFETCH(d ? 63 - (t+1) : t+1);
    }
    #undef PREFETCH
}

// ---------------- K3/K8: attention score via tf32 mma (3xTF32 split) ----------------
__global__ void __launch_bounds__(256) k_score_mma(int level, const float* __restrict__ bias,
                                                   const float* __restrict__ proj) {
    extern __shared__ __align__(16) float smem[];
    float2* sB   = (float2*)smem;            // [buf<2][hl<2][n<256][c<4] float2 = 32 KB
    float*  xs   = smem + 8192;              // 64 rows x 260 (padded) = 66560 B
    float*  sbias = xs + 64*260;
    float*  sproj = sbias + 256;
    float*  red   = sproj + 256;             // [64][2]

    const float*  x   = level ? g_out2 : g_out1;
    const float2* Bt  = level ? g_WW2t : g_WW1t;
    float*        out = level ? g_scores2 : g_scores1;
    const int rb = blockIdx.x, tid = threadIdx.x;
    const int w = tid >> 5, lane = tid & 31;
    const int gid = lane >> 2, tig = lane & 3;
    const int mt = w >> 1;
    const int nbase = (w & 1) * 128;

    sbias[tid] = bias[tid];
    sproj[tid] = proj[tid];

    for (int u = tid; u < 64*64; u += 256) {
        int i = u >> 6, f = u & 63;
        uint32_t da = (uint32_t)__cvta_generic_to_shared(&xs[i*260 + f*4]);
        const float4* src = ((const float4*)x) + (size_t)(rb*64 + i)*64 + f;
        asm volatile("cp.async.cg.shared.global [%0], [%1], 16;" :: "r"(da), "l"(src));
    }
    asm volatile("cp.async.commit_group;");

    #define STAGEB(KC, BUF) do {                                                     \
        const float2* sb_ = Bt + (KC)*2048;                                          \
        _Pragma("unroll")                                                            \
        for (int r_ = 0; r_ < 4; r_++) {                                             \
            int i_ = tid + 256*r_;                                                   \
            uint32_t da_ = (uint32_t)__cvta_generic_to_shared(sB + (BUF)*2048 + i_*2);\
            asm volatile("cp.async.cg.shared.global [%0], [%1], 16;"                 \
                         :: "r"(da_), "l"(sb_ + i_*2));                              \
        }                                                                            \
        asm volatile("cp.async.commit_group;");                                      \
    } while (0)

    STAGEB(0, 0);

    float c[16][4];
#pragma unroll
    for (int i = 0; i < 16; i++)
#pragma unroll
        for (int e = 0; e < 4; e++) c[i][e] = 0.f;

#pragma unroll 1
    for (int kc = 0; kc < 32; kc++) {
        const int cur = kc & 1;
        if (kc + 1 < 32) {
            STAGEB(kc + 1, (kc + 1) & 1);
            asm volatile("cp.async.wait_group 1;");
        } else {
            asm volatile("cp.async.wait_group 0;");
        }
        __syncthreads();

        const float* xr = xs + (mt*16 + gid)*260 + kc*8 + tig;
        float x0 = xr[0], x1 = xr[8*260], x2 = xr[4], x3 = xr[8*260 + 4];
        unsigned ah[4], al[4];
        ah[0] = tf32u(x0); ah[1] = tf32u(x1); ah[2] = tf32u(x2); ah[3] = tf32u(x3);
        al[0] = tf32u(x0 - __uint_as_float(ah[0]));
        al[1] = tf32u(x1 - __uint_as_float(ah[1]));
        al[2] = tf32u(x2 - __uint_as_float(ah[2]));
        al[3] = tf32u(x3 - __uint_as_float(ah[3]));

        const float2* bh = sB + (cur*2 + 0)*1024 + gid*4 + tig;
        const float2* bl = sB + (cur*2 + 1)*1024 + gid*4 + tig;
#pragma unroll
        for (int nt = 0; nt < 16; nt++) {
            const int off = nbase*4 + nt*32;
            float2 h  = bh[off];
            float2 lo = bl[off];
            unsigned b0 = __float_as_uint(h.x),  b1 = __float_as_uint(h.y);
            unsigned l0 = __float_as_uint(lo.x), l1 = __float_as_uint(lo.y);
            mma8(c[nt], ah, b0, b1);
            mma8(c[nt], al, b0, b1);
            mma8(c[nt], ah, l0, l1);
        }
        __syncthreads();
    }
    #undef STAGEB

    float s0 = 0.f, s1 = 0.f;
#pragma unroll
    for (int nt = 0; nt < 16; nt++) {
        int cn0 = nbase + nt*8 + 2*tig, cn1 = cn0 + 1;
        float b0 = sbias[cn0], b1 = sbias[cn1];
        float p0 = sproj[cn0], p1 = sproj[cn1];
        s0 += tanha(c[nt][0] + b0)*p0 + tanha(c[nt][1] + b1)*p1;
        s1 += tanha(c[nt][2] + b0)*p0 + tanha(c[nt][3] + b1)*p1;
    }
    s0 += __shfl_xor_sync(0xffffffffu, s0, 1);
    s0 += __shfl_xor_sync(0xffffffffu, s0, 2);
    s1 += __shfl_xor_sync(0xffffffffu, s1, 1);
    s1 += __shfl_xor_sync(0xffffffffu, s1, 2);
    if (tig == 0) {
        red[(mt*16 + gid)*2 + (w & 1)]     = s0;
        red[(mt*16 + gid + 8)*2 + (w & 1)] = s1;
    }
    __syncthreads();
    if (tid < 64) out[rb*64 + tid] = red[tid*2] + red[tid*2 + 1];
}

// ---------------- K4: softmax over tokens ----------------
__global__ void k_softmax() {
    const int s = blockIdx.x, b = threadIdx.x;
    const float* sc = g_scores1 + (size_t)s*64*64 + b;
    float m = -1e30f;
    for (int t = 0; t < 64; t++) m = fmaxf(m, sc[(size_t)t*64]);
    float sum = 0.f;
    for (int t = 0; t < 64; t++) sum += __expf(sc[(size_t)t*64] - m);
    float inv = __fdividef(1.f, sum);
    float* al = g_alpha1 + (size_t)s*64*64 + b;
    for (int t = 0; t < 64; t++) al[(size_t)t*64] = __expf(sc[(size_t)t*64] - m) * inv;
}

// ---------------- K5: sentence vectors ----------------
__global__ void k_sent() {
    const int blk = blockIdx.x, s = blk >> 6, b = blk & 63, h = threadIdx.x;
    float acc = 0.f;
    for (int t = 0; t < 64; t++) {
        float a = g_alpha1[(size_t)(s*64 + t)*64 + b];
        acc += a * g_out1[((size_t)(s*64 + t)*64 + b)*256 + h];
    }
    g_sent[(size_t)(s*64 + b)*256 + h] = acc;
}

// ---------------- K6: input-gate GEMM (inter), K=256 ----------------
__global__ void __launch_bounds__(384) k_xg2(const float* __restrict__ bih2) {
    __shared__ __align__(16) float xs[16][256];
    const int rb = blockIdx.x, d = blockIdx.y, tid = threadIdx.x;
    for (int u = tid; u < 16*64; u += 384) {
        int i = u >> 6, f = u & 63;
        ((float4*)xs[i])[f] = ((const float4*)g_sent)[(size_t)(rb*16 + i)*64 + f];
    }
    __syncthreads();
    const int g2 = tid % 192, rg = tid / 192;
    ull acc[16];
#pragma unroll
    for (int i = 0; i < 16; i++) acc[i] = 0ull;
    const ulonglong2* wp = g_Wih2p + d*(64*384);
#pragma unroll 1
    for (int q = 0; q < 64; q++) {
        ulonglong2 w0 = wp[q*384 + g2];
        ulonglong2 w1 = wp[q*384 + 192 + g2];
#pragma unroll
        for (int i = 0; i < 8; i++) {
            ulonglong2 x = ((const ulonglong2*)xs[rg*8 + i])[q];
            acc[2*i]   = ff2(x.x, w0.x, acc[2*i]);
            acc[2*i]   = ff2(x.y, w0.y, acc[2*i]);
            acc[2*i+1] = ff2(x.x, w1.x, acc[2*i+1]);
            acc[2*i+1] = ff2(x.y, w1.y, acc[2*i+1]);
        }
    }
    const float b0 = bih2[d*384 + g2], b1 = bih2[d*384 + 192 + g2];
#pragma unroll
    for (int i = 0; i < 8; i++) {
        float2 f0 = up2(acc[2*i]);
        float2 f1 = up2(acc[2*i+1]);
        float* op = g_xg2 + ((size_t)d*NROWS2 + rb*16 + rg*8 + i)*384;
        op[g2]       = f0.x + f0.y + b0;
        op[192 + g2] = f1.x + f1.y + b1;
    }
}

// ---------------- K7: inter biGRU (32 steps, BCHUNK=4) ----------------
__global__ void __launch_bounds__(384, 2) k_gru2(const float* __restrict__ bhh2) {
    __shared__ __align__(16) float hsm[4][128];
    __shared__ float ghs[4][384];
    const int bc = blockIdx.x, d = blockIdx.y, tid = threadIdx.x;
    for (int u = tid; u < 4*128; u += 384) ((float*)hsm)[u] = 0.f;
    const float bh = bhh2[d*384 + tid];
    const ulonglong2* wp = g_Whh2p + d*(32*384);
    __syncthreads();
    for (int t = 0; t < 32; t++) {
        const int tt = d ? (31 - t) : t;
        {
            const int g = tid;
            ull acc[4];
#pragma unroll
            for (int i = 0; i < 4; i++) acc[i] = 0ull;
#pragma unroll 1
            for (int q = 0; q < 32; q++) {
                ulonglong2 w = wp[q*384 + g];
#pragma unroll
                for (int i = 0; i < 4; i++) {
                    ulonglong2 x = ((const ulonglong2*)hsm[i])[q];
                    acc[i] = ff2(x.x, w.x, acc[i]);
                    acc[i] = ff2(x.y, w.y, acc[i]);
                }
            }
#pragma unroll
            for (int i = 0; i < 4; i++) {
                float2 f = up2(acc[i]);
                ghs[i][g] = f.x + f.y + bh;
            }
        }
        __syncthreads();
        if (tid < 128) {
            const int j = tid;
#pragma unroll 1
            for (int i = 0; i < 4; i++) {
                const int b = bc*4 + i;
                const float* xr = g_xg2 + ((size_t)d*NROWS2 + (size_t)tt*64 + b)*384;
                float r = sigm(xr[j]       + ghs[i][j]);
                float z = sigm(xr[128 + j] + ghs[i][128 + j]);
                float n = tanha(xr[256 + j] + r * ghs[i][256 + j]);
                float hp = hsm[i][j];
                float hn = (1.f - z) * n + z * hp;
                hsm[i][j] = hn;
                g_out2[((size_t)tt*64 + b)*256 + d*128 + j] = hn;
            }
        }
        __syncthreads();
    }
}

// ---------------- K9: doc vector ----------------
__global__ void k_doc() {
    const int b = blockIdx.x, h = threadIdx.x;
    float acc = 0.f;
    for (int s = 0; s < 32; s++)
        acc += g_scores2[s*64 + b] * g_out2[((size_t)(s*64 + b))*256 + h];
    g_doc[b*256 + h] = acc;
}

// ---------------- K10: final linear [64,5] ----------------
__global__ void k_final(const float* __restrict__ Wf, const float* __restrict__ bf,
                        float* __restrict__ out) {
    const int tid = threadIdx.x;
    if (tid >= 320) return;
    const int b = tid / 5, c = tid % 5;
    float acc = bf[c];
    for (int h = 0; h < 256; h++) acc += g_doc[b*256 + h] * Wf[c*256 + h];
    out[b*5 + c] = acc;
}

// ---------------- launch ----------------
extern "C" void kernel_launch(void* const* d_in, const int* in_sizes, int n_in,
                              void* d_out, int out_size) {
    const int*   tokens = (const int*)  d_in[0];
    const float* emb    = (const float*)d_in[1];
    const float* Wih1   = (const float*)d_in[2];
    const float* Whh1   = (const float*)d_in[3];
    const float* bih1   = (const float*)d_in[4];
    const float* bhh1   = (const float*)d_in[5];
    const float* WW1    = (const float*)d_in[6];
    const float* b1     = (const float*)d_in[7];
    const float* p1     = (const float*)d_in[8];
    const float* Wih2   = (const float*)d_in[9];
    const float* Whh2   = (const float*)d_in[10];
    const float* bih2   = (const float*)d_in[11];
    const float* bhh2   = (const float*)d_in[12];
    const float* WW2    = (const float*)d_in[13];
    const float* b2     = (const float*)d_in[14];
    const float* p2     = (const float*)d_in[15];
    const float* Wf     = (const float*)d_in[16];
    const float* bf     = (const float*)d_in[17];
    float* out = (float*)d_out;

    static int smem_set = 0;
    if (!smem_set) {
        cudaFuncSetAttribute(k_score_mma, cudaFuncAttributeMaxDynamicSharedMemorySize, 101888);
        smem_set = 1;
    }

    k_pack     <<<152, 256>>>(Wih1, Whh1, Wih2, Whh2);
    k_packtf   <<<256, 256>>>(WW1, WW2);
    k_vg       <<<2000, 768>>>(emb, bih1);
    k_gru1     <<<dim3(4, 2, 32), 256>>>(bhh1, tokens);
    k_score_mma<<<2048, 256, 101888>>>(0, b1, p1);
    k_softmax  <<<32, 64>>>();
    k_sent     <<<2048, 256>>>();
    k_xg2      <<<dim3(128, 2), 384>>>(bih2);
    k_gru2     <<<dim3(16, 2), 384>>>(bhh2);
    k_score_mma<<<32, 256, 101888>>>(1, b2, p2);
    k_doc      <<<64, 256>>>();
    k_final    <<<1, 512>>>(Wf, bf, out);
}